// round 1
// baseline (speedup 1.0000x reference)
#include <cuda_runtime.h>

#define PP 4
#define NN 65536
#define DD 128
#define OO 128
#define EE 500000
#define MM 32768
#define TOTAL_ROWS 655360   // 4*N + 12*M

// ---------------- scratch (static device arrays; no allocation) ----------------
__device__ float g_FN[(size_t)PP * NN * OO];        // feats @ W_neigh, per partition (134 MB)
__device__ float g_Agg[(size_t)TOTAL_ROWS * OO];    // per-block segment sums in O-space (335 MB)
__device__ float g_deg[TOTAL_ROWS];                 // per-block in-degrees
__device__ float g_SelfM[(size_t)PP * MM * OO];     // (feats@W_self + b) rows [0,M) per partition (67 MB)

// row offset of block (s,d) inside g_Agg/g_deg; block id k = s*4+d; diag blocks have N rows, off-diag M
__constant__ int c_blkoff[16] = {
    0,      65536,  98304,  131072,
    163840, 196608, 262144, 294912,
    327680, 360448, 393216, 458752,
    491520, 524288, 557056, 589824};
__constant__ int c_off_s[12] = {0,0,0, 1,1,1, 2,2,2, 3,3,3};
__constant__ int c_off_d[12] = {1,2,3, 0,2,3, 0,1,3, 0,1,2};

// ---------------- Phase A: fused GEMM  out[s] = feats[s]@Ws + b ;  FN[s] = feats[s]@Wn ----------
// grid: (N/128, 2, P); blockIdx.y==0 -> W_self (writes d_out + SelfM), ==1 -> W_neigh (writes g_FN)
__global__ __launch_bounds__(256) void gemm_self_fn(
    const float* __restrict__ feats, const float* __restrict__ Ws,
    const float* __restrict__ Wn, const float* __restrict__ bias,
    float* __restrict__ out)
{
    __shared__ float As[16][128];
    __shared__ float Bs[16][128];

    const int s    = blockIdx.z;
    const int row0 = blockIdx.x * 128;
    const bool isSelf = (blockIdx.y == 0);
    const float* A = feats + (size_t)s * NN * DD;
    const float* B = (isSelf ? Ws : Wn) + (size_t)s * DD * OO;

    const int t  = threadIdx.x;
    const int tx = t & 15;       // output col group
    const int ty = t >> 4;       // output row group

    float acc[8][8];
#pragma unroll
    for (int i = 0; i < 8; i++)
#pragma unroll
        for (int j = 0; j < 8; j++) acc[i][j] = 0.0f;

    for (int kt = 0; kt < 128; kt += 16) {
        // load A slab 128 rows x 16 k (transposed into As[k][m])
#pragma unroll
        for (int q = 0; q < 2; q++) {
            int idx = t * 2 + q;                 // 0..511
            int m  = idx >> 2;
            int kk = (idx & 3) * 4;
            float4 v = *(const float4*)(A + (size_t)(row0 + m) * DD + kt + kk);
            As[kk + 0][m] = v.x; As[kk + 1][m] = v.y;
            As[kk + 2][m] = v.z; As[kk + 3][m] = v.w;
        }
        // load B slab 16 k x 128 cols
#pragma unroll
        for (int q = 0; q < 2; q++) {
            int idx = t * 2 + q;
            int k  = idx >> 5;
            int nn = (idx & 31) * 4;
            *(float4*)&Bs[k][nn] = *(const float4*)(B + (size_t)(kt + k) * OO + nn);
        }
        __syncthreads();
#pragma unroll
        for (int k = 0; k < 16; k++) {
            float a[8], bb[8];
            *(float4*)(a)      = *(const float4*)&As[k][ty * 8];
            *(float4*)(a + 4)  = *(const float4*)&As[k][ty * 8 + 4];
            *(float4*)(bb)     = *(const float4*)&Bs[k][tx * 8];
            *(float4*)(bb + 4) = *(const float4*)&Bs[k][tx * 8 + 4];
#pragma unroll
            for (int i = 0; i < 8; i++)
#pragma unroll
                for (int j = 0; j < 8; j++)
                    acc[i][j] = fmaf(a[i], bb[j], acc[i][j]);
        }
        __syncthreads();
    }

    const int col0 = tx * 8;
    if (isSelf) {
#pragma unroll
        for (int i = 0; i < 8; i++) {
            int r = row0 + ty * 8 + i;
            float v[8];
#pragma unroll
            for (int j = 0; j < 8; j++) v[j] = acc[i][j] + bias[s * OO + col0 + j];
            float* orow = out + ((size_t)s * NN + r) * OO + col0;
            *(float4*)(orow)     = *(float4*)(v);
            *(float4*)(orow + 4) = *(float4*)(v + 4);
            if (r < MM) {
                float* srow = g_SelfM + ((size_t)s * MM + r) * OO + col0;
                *(float4*)(srow)     = *(float4*)(v);
                *(float4*)(srow + 4) = *(float4*)(v + 4);
            }
        }
    } else {
#pragma unroll
        for (int i = 0; i < 8; i++) {
            int r = row0 + ty * 8 + i;
            float* frow = g_FN + ((size_t)s * NN + r) * OO + col0;
            *(float4*)(frow)     = *(float4*)(&acc[i][0]);
            *(float4*)(frow + 4) = *(float4*)(&acc[i][4]);
        }
    }
}

// ---------------- Phase B: edge aggregation. One warp per edge. ----------------
// grid: 16*E/8 CTAs of 256 threads (8 warps)
__global__ __launch_bounds__(256) void agg_kernel(
    const int* __restrict__ e_src, const int* __restrict__ e_dst)
{
    const int lane = threadIdx.x & 31;
    const int e    = blockIdx.x * 8 + (threadIdx.x >> 5);   // flat edge id 0..16E-1
    const int blk  = e / EE;                                 // (s,d) block id
    const int s    = blk >> 2;

    const int src = __ldg(e_src + e);
    const int dst = __ldg(e_dst + e);

    float4 v = ((const float4*)(g_FN + ((size_t)s * NN + src) * OO))[lane];
    float* arow = g_Agg + ((size_t)(c_blkoff[blk] + dst)) * OO + lane * 4;
    asm volatile("red.global.add.v4.f32 [%0], {%1,%2,%3,%4};"
                 :: "l"(arow), "f"(v.x), "f"(v.y), "f"(v.z), "f"(v.w) : "memory");
    if (lane == 0)
        atomicAdd(g_deg + c_blkoff[blk] + dst, 1.0f);
}

// ---------------- Phase C1: diagonal combine (row-aligned, no atomics) ----------------
// grid: 4*N*32/256 CTAs; one thread per float4 of output
__global__ __launch_bounds__(256) void combine_diag(float* __restrict__ out)
{
    int tid = blockIdx.x * 256 + threadIdx.x;
    int c4  = tid & 31;
    int rg  = tid >> 5;                 // 0 .. 4N-1
    int d   = rg >> 16;
    int r   = rg & (NN - 1);
    size_t arow = (size_t)c_blkoff[d * 5] + r;
    float invd = 1.0f / fmaxf(g_deg[arow], 1.0f);
    float4 a = ((const float4*)(g_Agg + arow * OO))[c4];
    float4* o = ((float4*)(out + ((size_t)d * NN + r) * OO)) + c4;
    float4 v = *o;
    v.x = fmaf(a.x, invd, v.x);
    v.y = fmaf(a.y, invd, v.y);
    v.z = fmaf(a.z, invd, v.z);
    v.w = fmaf(a.w, invd, v.w);
    *o = v;
}

// ---------------- Phase C2: off-diagonal scatter-merge ----------------
// grid: 12*M*32/256 CTAs; atomics because different source blocks may hit the same target row
__global__ __launch_bounds__(256) void combine_offdiag(
    float* __restrict__ out, const int* __restrict__ merge)
{
    int tid = blockIdx.x * 256 + threadIdx.x;
    int c4  = tid & 31;
    int idx = tid >> 5;                 // 0 .. 12M-1
    int ob  = idx >> 15;                // off-diag pair index
    int r   = idx & (MM - 1);
    int s = c_off_s[ob], d = c_off_d[ob];
    int blk = s * 4 + d;
    size_t arow = (size_t)c_blkoff[blk] + r;
    float invd = 1.0f / fmaxf(g_deg[arow], 1.0f);
    float4 a  = ((const float4*)(g_Agg + arow * OO))[c4];
    float4 sm = ((const float4*)(g_SelfM + ((size_t)s * MM + r) * OO))[c4];
    float4 v;
    v.x = fmaf(a.x, invd, sm.x);
    v.y = fmaf(a.y, invd, sm.y);
    v.z = fmaf(a.z, invd, sm.z);
    v.w = fmaf(a.w, invd, sm.w);
    int tgt = __ldg(merge + (size_t)blk * MM + r);
    float* op = out + ((size_t)d * NN + tgt) * OO + c4 * 4;
    asm volatile("red.global.add.v4.f32 [%0], {%1,%2,%3,%4};"
                 :: "l"(op), "f"(v.x), "f"(v.y), "f"(v.z), "f"(v.w) : "memory");
}

// ---------------- launch ----------------
extern "C" void kernel_launch(void* const* d_in, const int* in_sizes, int n_in,
                              void* d_out, int out_size)
{
    const float* feats  = (const float*)d_in[0];   // [P,N,D]
    const float* Wself  = (const float*)d_in[1];   // [P,D,O]
    const float* Wneigh = (const float*)d_in[2];   // [P,D,O]
    const float* bias   = (const float*)d_in[3];   // [P,O]
    const int*   e_src  = (const int*)d_in[4];     // [P,P,E]
    const int*   e_dst  = (const int*)d_in[5];     // [P,P,E]
    const int*   merge  = (const int*)d_in[6];     // [P,P,M]
    float* out = (float*)d_out;                    // [P,N,O]

    void* aggPtr = nullptr; cudaGetSymbolAddress(&aggPtr, g_Agg);
    void* degPtr = nullptr; cudaGetSymbolAddress(&degPtr, g_deg);
    cudaMemsetAsync(aggPtr, 0, sizeof(float) * (size_t)TOTAL_ROWS * OO, 0);
    cudaMemsetAsync(degPtr, 0, sizeof(float) * (size_t)TOTAL_ROWS, 0);

    gemm_self_fn<<<dim3(NN / 128, 2, PP), 256>>>(feats, Wself, Wneigh, bias, out);
    agg_kernel<<<(16 * EE) / 8, 256>>>(e_src, e_dst);
    combine_diag<<<(4 * NN * 32) / 256, 256>>>(out);
    combine_offdiag<<<(12 * MM * 32) / 256, 256>>>(out, merge);
}

// round 2
// speedup vs baseline: 1.6164x; 1.6164x over previous
#include <cuda_runtime.h>

#define PP 4
#define NN 65536
#define DD 128
#define OO 128
#define EE 500000
#define MM 32768
#define TOTAL_ROWS 655360   // 4*N + 12*M
#define NEDGES (16 * EE)    // 8,000,000

// ---------------- scratch (static device arrays; no allocation) ----------------
__device__ float g_FN[(size_t)PP * NN * OO];        // feats @ W_neigh, per partition (134 MB)
__device__ float g_SelfM[(size_t)PP * MM * OO];     // (feats@W_self + b) rows [0,M) per partition (67 MB)
__device__ int   g_cnt[TOTAL_ROWS];                 // per-row in-degree (histogram)
__device__ int   g_off[TOTAL_ROWS];                 // CSR offsets (exclusive scan of cnt)
__device__ int   g_cur[TOTAL_ROWS];                 // scatter cursors
__device__ int   g_part[1024];                      // scan block partials
__device__ int   g_sorted_src[NEDGES];              // edge src ids sorted by dst row (32 MB)

// row offset of block (s,d); block id k = s*4+d; diag blocks N rows, off-diag M rows
__constant__ int c_blkoff[17] = {
    0,      65536,  98304,  131072,
    163840, 196608, 262144, 294912,
    327680, 360448, 393216, 458752,
    491520, 524288, 557056, 589824, 655360};

// ---------------- Phase A: fused GEMM  out[s] = feats[s]@Ws + b ;  FN[s] = feats[s]@Wn ----------
__global__ __launch_bounds__(256) void gemm_self_fn(
    const float* __restrict__ feats, const float* __restrict__ Ws,
    const float* __restrict__ Wn, const float* __restrict__ bias,
    float* __restrict__ out)
{
    __shared__ float As[16][128];
    __shared__ float Bs[16][128];

    const int s    = blockIdx.z;
    const int row0 = blockIdx.x * 128;
    const bool isSelf = (blockIdx.y == 0);
    const float* A = feats + (size_t)s * NN * DD;
    const float* B = (isSelf ? Ws : Wn) + (size_t)s * DD * OO;

    const int t  = threadIdx.x;
    const int tx = t & 15;
    const int ty = t >> 4;

    float acc[8][8];
#pragma unroll
    for (int i = 0; i < 8; i++)
#pragma unroll
        for (int j = 0; j < 8; j++) acc[i][j] = 0.0f;

    for (int kt = 0; kt < 128; kt += 16) {
#pragma unroll
        for (int q = 0; q < 2; q++) {
            int idx = t * 2 + q;
            int m  = idx >> 2;
            int kk = (idx & 3) * 4;
            float4 v = *(const float4*)(A + (size_t)(row0 + m) * DD + kt + kk);
            As[kk + 0][m] = v.x; As[kk + 1][m] = v.y;
            As[kk + 2][m] = v.z; As[kk + 3][m] = v.w;
        }
#pragma unroll
        for (int q = 0; q < 2; q++) {
            int idx = t * 2 + q;
            int k  = idx >> 5;
            int nn = (idx & 31) * 4;
            *(float4*)&Bs[k][nn] = *(const float4*)(B + (size_t)(kt + k) * OO + nn);
        }
        __syncthreads();
#pragma unroll
        for (int k = 0; k < 16; k++) {
            float a[8], bb[8];
            *(float4*)(a)      = *(const float4*)&As[k][ty * 8];
            *(float4*)(a + 4)  = *(const float4*)&As[k][ty * 8 + 4];
            *(float4*)(bb)     = *(const float4*)&Bs[k][tx * 8];
            *(float4*)(bb + 4) = *(const float4*)&Bs[k][tx * 8 + 4];
#pragma unroll
            for (int i = 0; i < 8; i++)
#pragma unroll
                for (int j = 0; j < 8; j++)
                    acc[i][j] = fmaf(a[i], bb[j], acc[i][j]);
        }
        __syncthreads();
    }

    const int col0 = tx * 8;
    if (isSelf) {
#pragma unroll
        for (int i = 0; i < 8; i++) {
            int r = row0 + ty * 8 + i;
            float v[8];
#pragma unroll
            for (int j = 0; j < 8; j++) v[j] = acc[i][j] + bias[s * OO + col0 + j];
            float* orow = out + ((size_t)s * NN + r) * OO + col0;
            *(float4*)(orow)     = *(float4*)(v);
            *(float4*)(orow + 4) = *(float4*)(v + 4);
            if (r < MM) {
                float* srow = g_SelfM + ((size_t)s * MM + r) * OO + col0;
                *(float4*)(srow)     = *(float4*)(v);
                *(float4*)(srow + 4) = *(float4*)(v + 4);
            }
        }
    } else {
#pragma unroll
        for (int i = 0; i < 8; i++) {
            int r = row0 + ty * 8 + i;
            float* frow = g_FN + ((size_t)s * NN + r) * OO + col0;
            *(float4*)(frow)     = *(float4*)(&acc[i][0]);
            *(float4*)(frow + 4) = *(float4*)(&acc[i][4]);
        }
    }
}

// ---------------- Sort pipeline ----------------
__global__ __launch_bounds__(256) void hist_kernel(const int* __restrict__ e_dst)
{
    int e = blockIdx.x * 256 + threadIdx.x;
    int blk = e / EE;
    int row = c_blkoff[blk] + __ldg(e_dst + e);
    atomicAdd(&g_cnt[row], 1);
}

// scan1: per-block (1024 elems) inclusive scan -> exclusive out + block partial
__global__ __launch_bounds__(1024) void scan1_kernel()
{
    __shared__ int sm[1024];
    int tid = threadIdx.x;
    int i = blockIdx.x * 1024 + tid;
    int v = g_cnt[i];
    sm[tid] = v;
    __syncthreads();
    for (int ofs = 1; ofs < 1024; ofs <<= 1) {
        int t = (tid >= ofs) ? sm[tid - ofs] : 0;
        __syncthreads();
        sm[tid] += t;
        __syncthreads();
    }
    g_off[i] = sm[tid] - v;               // exclusive
    if (tid == 1023) g_part[blockIdx.x] = sm[1023];
}

// scan2: exclusive scan of 640 partials in one block
__global__ __launch_bounds__(1024) void scan2_kernel()
{
    __shared__ int sm[1024];
    int tid = threadIdx.x;
    int v = (tid < 640) ? g_part[tid] : 0;
    sm[tid] = v;
    __syncthreads();
    for (int ofs = 1; ofs < 1024; ofs <<= 1) {
        int t = (tid >= ofs) ? sm[tid - ofs] : 0;
        __syncthreads();
        sm[tid] += t;
        __syncthreads();
    }
    if (tid < 640) g_part[tid] = sm[tid] - v;   // exclusive
}

// scan3: add block base, init cursor
__global__ __launch_bounds__(1024) void scan3_kernel()
{
    int i = blockIdx.x * 1024 + threadIdx.x;
    int o = g_off[i] + g_part[blockIdx.x];
    g_off[i] = o;
    g_cur[i] = o;
}

__global__ __launch_bounds__(256) void scatter_kernel(
    const int* __restrict__ e_src, const int* __restrict__ e_dst)
{
    int e = blockIdx.x * 256 + threadIdx.x;
    int blk = e / EE;
    int row = c_blkoff[blk] + __ldg(e_dst + e);
    int pos = atomicAdd(&g_cur[row], 1);
    g_sorted_src[pos] = __ldg(e_src + e);
}

// ---------------- Phase B+C fused: warp per destination row ----------------
__global__ __launch_bounds__(256) void agg_combine(
    float* __restrict__ out, const int* __restrict__ merge)
{
    const int lane = threadIdx.x & 31;
    const int r = blockIdx.x * 8 + (threadIdx.x >> 5);    // flat row 0..TOTAL_ROWS-1

    int blk = 0;
#pragma unroll
    for (int k = 1; k < 16; k++)
        if (r >= c_blkoff[k]) blk = k;
    const int s = blk >> 2, d = blk & 3;
    const int lrow = r - c_blkoff[blk];

    const int base = g_off[r];
    const int deg  = g_cnt[r];
    const float* FNs = g_FN + (size_t)s * NN * OO;

    float4 acc = make_float4(0.f, 0.f, 0.f, 0.f);
    for (int i0 = 0; i0 < deg; i0 += 32) {
        int mi = i0 + lane;
        int msrc = (mi < deg) ? __ldg(g_sorted_src + base + mi) : 0;
        int cnt = min(32, deg - i0);
        for (int j = 0; j < cnt; j++) {
            int src = __shfl_sync(0xffffffffu, msrc, j);
            float4 v = ((const float4*)(FNs + (size_t)src * OO))[lane];
            acc.x += v.x; acc.y += v.y; acc.z += v.z; acc.w += v.w;
        }
    }

    const float invd = (deg > 0) ? (1.0f / (float)deg) : 0.0f;

    if (s == d) {
        if (deg == 0) return;  // nothing to add; Self already in out
        float* op = out + ((size_t)d * NN + lrow) * OO + lane * 4;
        asm volatile("red.global.add.v4.f32 [%0], {%1,%2,%3,%4};"
                     :: "l"(op), "f"(acc.x * invd), "f"(acc.y * invd),
                        "f"(acc.z * invd), "f"(acc.w * invd) : "memory");
    } else {
        float4 sm = ((const float4*)(g_SelfM + ((size_t)s * MM + lrow) * OO))[lane];
        float4 v;
        v.x = fmaf(acc.x, invd, sm.x);
        v.y = fmaf(acc.y, invd, sm.y);
        v.z = fmaf(acc.z, invd, sm.z);
        v.w = fmaf(acc.w, invd, sm.w);
        int tgt = __ldg(merge + (size_t)blk * MM + lrow);
        float* op = out + ((size_t)d * NN + tgt) * OO + lane * 4;
        asm volatile("red.global.add.v4.f32 [%0], {%1,%2,%3,%4};"
                     :: "l"(op), "f"(v.x), "f"(v.y), "f"(v.z), "f"(v.w) : "memory");
    }
}

// ---------------- launch ----------------
extern "C" void kernel_launch(void* const* d_in, const int* in_sizes, int n_in,
                              void* d_out, int out_size)
{
    const float* feats  = (const float*)d_in[0];   // [P,N,D]
    const float* Wself  = (const float*)d_in[1];   // [P,D,O]
    const float* Wneigh = (const float*)d_in[2];   // [P,D,O]
    const float* bias   = (const float*)d_in[3];   // [P,O]
    const int*   e_src  = (const int*)d_in[4];     // [P,P,E]
    const int*   e_dst  = (const int*)d_in[5];     // [P,P,E]
    const int*   merge  = (const int*)d_in[6];     // [P,P,M]
    float* out = (float*)d_out;                    // [P,N,O]

    void* cntPtr = nullptr; cudaGetSymbolAddress(&cntPtr, g_cnt);
    cudaMemsetAsync(cntPtr, 0, sizeof(int) * (size_t)TOTAL_ROWS, 0);

    gemm_self_fn<<<dim3(NN / 128, 2, PP), 256>>>(feats, Wself, Wneigh, bias, out);

    hist_kernel<<<NEDGES / 256, 256>>>(e_dst);
    scan1_kernel<<<TOTAL_ROWS / 1024, 1024>>>();
    scan2_kernel<<<1, 1024>>>();
    scan3_kernel<<<TOTAL_ROWS / 1024, 1024>>>();
    scatter_kernel<<<NEDGES / 256, 256>>>(e_src, e_dst);

    agg_combine<<<TOTAL_ROWS / 8, 256>>>(out, merge);
}

// round 3
// speedup vs baseline: 1.8270x; 1.1303x over previous
#include <cuda_runtime.h>
#include <cuda_bf16.h>

#define PP 4
#define NN 65536
#define DD 128
#define OO 128
#define EE 500000
#define MM 32768
#define TOTAL_ROWS 655360   // 4*N + 12*M
#define NEDGES (16 * EE)    // 8,000,000

// ---------------- scratch (static device arrays; no allocation) ----------------
__device__ __nv_bfloat16 g_FN[(size_t)PP * NN * OO]; // feats @ W_neigh, bf16 (67 MB)
__device__ float g_SelfM[(size_t)PP * MM * OO];      // (feats@W_self + b) rows [0,M) (67 MB)
__device__ int   g_cnt[TOTAL_ROWS];                  // per-row in-degree (histogram)
__device__ int   g_off[TOTAL_ROWS];                  // CSR offsets (exclusive scan of cnt)
__device__ int   g_cur[TOTAL_ROWS];                  // scatter cursors
__device__ int   g_part[1024];                       // scan block partials
__device__ int   g_sorted_src[NEDGES];               // edge src ids sorted by dst row (32 MB)

// row offset of block (s,d); block id k = s*4+d; diag blocks N rows, off-diag M rows
__constant__ int c_blkoff[17] = {
    0,      65536,  98304,  131072,
    163840, 196608, 262144, 294912,
    327680, 360448, 393216, 458752,
    491520, 524288, 557056, 589824, 655360};

// ---------------- Phase A: fused GEMM  out[s] = feats[s]@Ws + b ;  FN[s] = feats[s]@Wn ----------
__global__ __launch_bounds__(256) void gemm_self_fn(
    const float* __restrict__ feats, const float* __restrict__ Ws,
    const float* __restrict__ Wn, const float* __restrict__ bias,
    float* __restrict__ out)
{
    __shared__ float As[16][128];
    __shared__ float Bs[16][128];

    const int s    = blockIdx.z;
    const int row0 = blockIdx.x * 128;
    const bool isSelf = (blockIdx.y == 0);
    const float* A = feats + (size_t)s * NN * DD;
    const float* B = (isSelf ? Ws : Wn) + (size_t)s * DD * OO;

    const int t  = threadIdx.x;
    const int tx = t & 15;
    const int ty = t >> 4;

    float acc[8][8];
#pragma unroll
    for (int i = 0; i < 8; i++)
#pragma unroll
        for (int j = 0; j < 8; j++) acc[i][j] = 0.0f;

    for (int kt = 0; kt < 128; kt += 16) {
#pragma unroll
        for (int q = 0; q < 2; q++) {
            int idx = t * 2 + q;
            int m  = idx >> 2;
            int kk = (idx & 3) * 4;
            float4 v = *(const float4*)(A + (size_t)(row0 + m) * DD + kt + kk);
            As[kk + 0][m] = v.x; As[kk + 1][m] = v.y;
            As[kk + 2][m] = v.z; As[kk + 3][m] = v.w;
        }
#pragma unroll
        for (int q = 0; q < 2; q++) {
            int idx = t * 2 + q;
            int k  = idx >> 5;
            int nn = (idx & 31) * 4;
            *(float4*)&Bs[k][nn] = *(const float4*)(B + (size_t)(kt + k) * OO + nn);
        }
        __syncthreads();
#pragma unroll
        for (int k = 0; k < 16; k++) {
            float a[8], bb[8];
            *(float4*)(a)      = *(const float4*)&As[k][ty * 8];
            *(float4*)(a + 4)  = *(const float4*)&As[k][ty * 8 + 4];
            *(float4*)(bb)     = *(const float4*)&Bs[k][tx * 8];
            *(float4*)(bb + 4) = *(const float4*)&Bs[k][tx * 8 + 4];
#pragma unroll
            for (int i = 0; i < 8; i++)
#pragma unroll
                for (int j = 0; j < 8; j++)
                    acc[i][j] = fmaf(a[i], bb[j], acc[i][j]);
        }
        __syncthreads();
    }

    const int col0 = tx * 8;
    if (isSelf) {
#pragma unroll
        for (int i = 0; i < 8; i++) {
            int r = row0 + ty * 8 + i;
            float v[8];
#pragma unroll
            for (int j = 0; j < 8; j++) v[j] = acc[i][j] + bias[s * OO + col0 + j];
            float* orow = out + ((size_t)s * NN + r) * OO + col0;
            *(float4*)(orow)     = *(float4*)(v);
            *(float4*)(orow + 4) = *(float4*)(v + 4);
            if (r < MM) {
                float* srow = g_SelfM + ((size_t)s * MM + r) * OO + col0;
                *(float4*)(srow)     = *(float4*)(v);
                *(float4*)(srow + 4) = *(float4*)(v + 4);
            }
        }
    } else {
#pragma unroll
        for (int i = 0; i < 8; i++) {
            int r = row0 + ty * 8 + i;
            __nv_bfloat16* frow = g_FN + ((size_t)s * NN + r) * OO + col0;
            __nv_bfloat162 p[4];
#pragma unroll
            for (int j = 0; j < 4; j++)
                p[j] = __floats2bfloat162_rn(acc[i][2 * j], acc[i][2 * j + 1]);
            *(uint4*)frow = *(uint4*)p;
        }
    }
}

// ---------------- Sort pipeline ----------------
__global__ __launch_bounds__(256) void hist_kernel(const int* __restrict__ e_dst)
{
    int e = blockIdx.x * 256 + threadIdx.x;
    int blk = e / EE;
    int row = c_blkoff[blk] + __ldg(e_dst + e);
    atomicAdd(&g_cnt[row], 1);
}

__global__ __launch_bounds__(1024) void scan1_kernel()
{
    __shared__ int sm[1024];
    int tid = threadIdx.x;
    int i = blockIdx.x * 1024 + tid;
    int v = g_cnt[i];
    sm[tid] = v;
    __syncthreads();
    for (int ofs = 1; ofs < 1024; ofs <<= 1) {
        int t = (tid >= ofs) ? sm[tid - ofs] : 0;
        __syncthreads();
        sm[tid] += t;
        __syncthreads();
    }
    g_off[i] = sm[tid] - v;               // exclusive
    if (tid == 1023) g_part[blockIdx.x] = sm[1023];
}

__global__ __launch_bounds__(1024) void scan2_kernel()
{
    __shared__ int sm[1024];
    int tid = threadIdx.x;
    int v = (tid < 640) ? g_part[tid] : 0;
    sm[tid] = v;
    __syncthreads();
    for (int ofs = 1; ofs < 1024; ofs <<= 1) {
        int t = (tid >= ofs) ? sm[tid - ofs] : 0;
        __syncthreads();
        sm[tid] += t;
        __syncthreads();
    }
    if (tid < 640) g_part[tid] = sm[tid] - v;   // exclusive
}

__global__ __launch_bounds__(1024) void scan3_kernel()
{
    int i = blockIdx.x * 1024 + threadIdx.x;
    int o = g_off[i] + g_part[blockIdx.x];
    g_off[i] = o;
    g_cur[i] = o;
}

__global__ __launch_bounds__(256) void scatter_kernel(
    const int* __restrict__ e_src, const int* __restrict__ e_dst)
{
    int e = blockIdx.x * 256 + threadIdx.x;
    int blk = e / EE;
    int row = c_blkoff[blk] + __ldg(e_dst + e);
    int pos = atomicAdd(&g_cur[row], 1);
    g_sorted_src[pos] = __ldg(e_src + e);
}

// ---------------- Phase B+C fused: warp per destination row, bf16 gather ----------------
__global__ __launch_bounds__(256) void agg_combine(
    float* __restrict__ out, const int* __restrict__ merge)
{
    const int lane = threadIdx.x & 31;
    const int r = blockIdx.x * 8 + (threadIdx.x >> 5);    // flat row 0..TOTAL_ROWS-1

    int blk = 0;
#pragma unroll
    for (int k = 1; k < 16; k++)
        if (r >= c_blkoff[k]) blk = k;
    const int s = blk >> 2, d = blk & 3;
    const int lrow = r - c_blkoff[blk];

    const int base = g_off[r];
    const int deg  = g_cnt[r];
    const uint2* FNs = (const uint2*)(g_FN + (size_t)s * NN * OO);   // 32 uint2 per row

    float4 acc = make_float4(0.f, 0.f, 0.f, 0.f);
    for (int i0 = 0; i0 < deg; i0 += 32) {
        int mi = i0 + lane;
        int msrc = (mi < deg) ? __ldg(g_sorted_src + base + mi) : 0;
        int cnt = min(32, deg - i0);
        for (int j = 0; j < cnt; j++) {
            int src = __shfl_sync(0xffffffffu, msrc, j);
            uint2 raw = __ldg(FNs + (size_t)src * 32 + lane);
            __nv_bfloat162 h0 = *(__nv_bfloat162*)&raw.x;
            __nv_bfloat162 h1 = *(__nv_bfloat162*)&raw.y;
            float2 f0 = __bfloat1622float2(h0);
            float2 f1 = __bfloat1622float2(h1);
            acc.x += f0.x; acc.y += f0.y; acc.z += f1.x; acc.w += f1.y;
        }
    }

    const float invd = (deg > 0) ? (1.0f / (float)deg) : 0.0f;

    if (s == d) {
        if (deg == 0) return;  // nothing to add; Self already in out
        float* op = out + ((size_t)d * NN + lrow) * OO + lane * 4;
        asm volatile("red.global.add.v4.f32 [%0], {%1,%2,%3,%4};"
                     :: "l"(op), "f"(acc.x * invd), "f"(acc.y * invd),
                        "f"(acc.z * invd), "f"(acc.w * invd) : "memory");
    } else {
        float4 sm = ((const float4*)(g_SelfM + ((size_t)s * MM + lrow) * OO))[lane];
        float4 v;
        v.x = fmaf(acc.x, invd, sm.x);
        v.y = fmaf(acc.y, invd, sm.y);
        v.z = fmaf(acc.z, invd, sm.z);
        v.w = fmaf(acc.w, invd, sm.w);
        int tgt = __ldg(merge + (size_t)blk * MM + lrow);
        float* op = out + ((size_t)d * NN + tgt) * OO + lane * 4;
        asm volatile("red.global.add.v4.f32 [%0], {%1,%2,%3,%4};"
                     :: "l"(op), "f"(v.x), "f"(v.y), "f"(v.z), "f"(v.w) : "memory");
    }
}

// ---------------- launch ----------------
extern "C" void kernel_launch(void* const* d_in, const int* in_sizes, int n_in,
                              void* d_out, int out_size)
{
    const float* feats  = (const float*)d_in[0];   // [P,N,D]
    const float* Wself  = (const float*)d_in[1];   // [P,D,O]
    const float* Wneigh = (const float*)d_in[2];   // [P,D,O]
    const float* bias   = (const float*)d_in[3];   // [P,O]
    const int*   e_src  = (const int*)d_in[4];     // [P,P,E]
    const int*   e_dst  = (const int*)d_in[5];     // [P,P,E]
    const int*   merge  = (const int*)d_in[6];     // [P,P,M]
    float* out = (float*)d_out;                    // [P,N,O]

    void* cntPtr = nullptr; cudaGetSymbolAddress(&cntPtr, g_cnt);
    cudaMemsetAsync(cntPtr, 0, sizeof(int) * (size_t)TOTAL_ROWS, 0);

    gemm_self_fn<<<dim3(NN / 128, 2, PP), 256>>>(feats, Wself, Wneigh, bias, out);

    hist_kernel<<<NEDGES / 256, 256>>>(e_dst);
    scan1_kernel<<<TOTAL_ROWS / 1024, 1024>>>();
    scan2_kernel<<<1, 1024>>>();
    scan3_kernel<<<TOTAL_ROWS / 1024, 1024>>>();
    scatter_kernel<<<NEDGES / 256, 256>>>(e_src, e_dst);

    agg_combine<<<TOTAL_ROWS / 8, 256>>>(out, merge);
}

// round 4
// speedup vs baseline: 1.8317x; 1.0026x over previous
#include <cuda_runtime.h>
#include <cuda_bf16.h>
#include <cuda_fp16.h>

#define PP 4
#define NN 65536
#define DD 128
#define OO 128
#define EE 500000
#define MM 32768
#define TOTAL_ROWS 655360   // 4*N + 12*M
#define NEDGES (16 * EE)    // 8,000,000

// ---------------- scratch (static device arrays; no allocation) ----------------
__device__ __half g_FN[(size_t)PP * NN * OO];        // feats @ W_neigh, fp16 (67 MB)
__device__ float g_SelfM[(size_t)PP * MM * OO];      // (feats@W_self + b) rows [0,M) (67 MB)
__device__ int   g_cnt[TOTAL_ROWS];                  // per-row in-degree (histogram)
__device__ int   g_off[TOTAL_ROWS];                  // CSR offsets (exclusive scan of cnt)
__device__ int   g_cur[TOTAL_ROWS];                  // scatter cursors
__device__ int   g_part[1024];                       // scan block partials
__device__ int   g_sorted_src[NEDGES];               // edge src ids sorted by dst row (32 MB)

// row offset of block (s,d); block id k = s*4+d; diag blocks N rows, off-diag M rows
__constant__ int c_blkoff[17] = {
    0,      65536,  98304,  131072,
    163840, 196608, 262144, 294912,
    327680, 360448, 393216, 458752,
    491520, 524288, 557056, 589824, 655360};

// ---------------- Phase A: fused GEMM with packed f32x2 FMA ----------------
// out[s] = feats[s]@Ws + b (fp32, + SelfM copy); FN[s] = feats[s]@Wn (fp16)
__global__ __launch_bounds__(256) void gemm_self_fn(
    const float* __restrict__ feats, const float* __restrict__ Ws,
    const float* __restrict__ Wn, const float* __restrict__ bias,
    float* __restrict__ out)
{
    __shared__ float As[16][128];
    __shared__ float Bs[16][128];

    const int s    = blockIdx.z;
    const int row0 = blockIdx.x * 128;
    const bool isSelf = (blockIdx.y == 0);
    const float* A = feats + (size_t)s * NN * DD;
    const float* B = (isSelf ? Ws : Wn) + (size_t)s * DD * OO;

    const int t  = threadIdx.x;
    const int tx = t & 15;       // col group (8 cols)
    const int ty = t >> 4;       // row group (8 rows)

    // packed accumulators: acc2[i][j] holds cols {2j, 2j+1} for row i
    unsigned long long acc2[8][4];
#pragma unroll
    for (int i = 0; i < 8; i++)
#pragma unroll
        for (int j = 0; j < 4; j++) acc2[i][j] = 0ULL;

    for (int kt = 0; kt < 128; kt += 16) {
#pragma unroll
        for (int q = 0; q < 2; q++) {
            int idx = t * 2 + q;
            int m  = idx >> 2;
            int kk = (idx & 3) * 4;
            float4 v = *(const float4*)(A + (size_t)(row0 + m) * DD + kt + kk);
            As[kk + 0][m] = v.x; As[kk + 1][m] = v.y;
            As[kk + 2][m] = v.z; As[kk + 3][m] = v.w;
        }
#pragma unroll
        for (int q = 0; q < 2; q++) {
            int idx = t * 2 + q;
            int k  = idx >> 5;
            int nn = (idx & 31) * 4;
            *(float4*)&Bs[k][nn] = *(const float4*)(B + (size_t)(kt + k) * OO + nn);
        }
        __syncthreads();
#pragma unroll
        for (int k = 0; k < 16; k++) {
            float av[8];
            *(float4*)(av)     = *(const float4*)&As[k][ty * 8];
            *(float4*)(av + 4) = *(const float4*)&As[k][ty * 8 + 4];
            // b pairs come directly from 16B smem loads: (b0,b1),(b2,b3),(b4,b5),(b6,b7)
            ulonglong2 bp01 = *(const ulonglong2*)&Bs[k][tx * 8];
            ulonglong2 bp23 = *(const ulonglong2*)&Bs[k][tx * 8 + 4];
#pragma unroll
            for (int i = 0; i < 8; i++) {
                unsigned long long ap;
                asm("mov.b64 %0, {%1, %1};" : "=l"(ap) : "f"(av[i]));
                asm("fma.rn.f32x2 %0, %1, %2, %0;" : "+l"(acc2[i][0]) : "l"(ap), "l"(bp01.x));
                asm("fma.rn.f32x2 %0, %1, %2, %0;" : "+l"(acc2[i][1]) : "l"(ap), "l"(bp01.y));
                asm("fma.rn.f32x2 %0, %1, %2, %0;" : "+l"(acc2[i][2]) : "l"(ap), "l"(bp23.x));
                asm("fma.rn.f32x2 %0, %1, %2, %0;" : "+l"(acc2[i][3]) : "l"(ap), "l"(bp23.y));
            }
        }
        __syncthreads();
    }

    const int col0 = tx * 8;
    if (isSelf) {
#pragma unroll
        for (int i = 0; i < 8; i++) {
            int r = row0 + ty * 8 + i;
            float v[8];
#pragma unroll
            for (int j = 0; j < 4; j++) {
                float lo, hi;
                asm("mov.b64 {%0, %1}, %2;" : "=f"(lo), "=f"(hi) : "l"(acc2[i][j]));
                v[2 * j]     = lo + bias[s * OO + col0 + 2 * j];
                v[2 * j + 1] = hi + bias[s * OO + col0 + 2 * j + 1];
            }
            float* orow = out + ((size_t)s * NN + r) * OO + col0;
            *(float4*)(orow)     = *(float4*)(v);
            *(float4*)(orow + 4) = *(float4*)(v + 4);
            if (r < MM) {
                float* srow = g_SelfM + ((size_t)s * MM + r) * OO + col0;
                *(float4*)(srow)     = *(float4*)(v);
                *(float4*)(srow + 4) = *(float4*)(v + 4);
            }
        }
    } else {
#pragma unroll
        for (int i = 0; i < 8; i++) {
            int r = row0 + ty * 8 + i;
            __half* frow = g_FN + ((size_t)s * NN + r) * OO + col0;
            __half2 p[4];
#pragma unroll
            for (int j = 0; j < 4; j++) {
                float lo, hi;
                asm("mov.b64 {%0, %1}, %2;" : "=f"(lo), "=f"(hi) : "l"(acc2[i][j]));
                p[j] = __floats2half2_rn(lo, hi);
            }
            *(uint4*)frow = *(uint4*)p;
        }
    }
}

// ---------------- Sort pipeline ----------------
__global__ __launch_bounds__(256) void hist_kernel(const int* __restrict__ e_dst)
{
    int e = blockIdx.x * 256 + threadIdx.x;
    int blk = e / EE;
    int row = c_blkoff[blk] + __ldg(e_dst + e);
    atomicAdd(&g_cnt[row], 1);
}

__global__ __launch_bounds__(1024) void scan1_kernel()
{
    __shared__ int sm[1024];
    int tid = threadIdx.x;
    int i = blockIdx.x * 1024 + tid;
    int v = g_cnt[i];
    sm[tid] = v;
    __syncthreads();
    for (int ofs = 1; ofs < 1024; ofs <<= 1) {
        int t = (tid >= ofs) ? sm[tid - ofs] : 0;
        __syncthreads();
        sm[tid] += t;
        __syncthreads();
    }
    g_off[i] = sm[tid] - v;               // exclusive
    if (tid == 1023) g_part[blockIdx.x] = sm[1023];
}

__global__ __launch_bounds__(1024) void scan2_kernel()
{
    __shared__ int sm[1024];
    int tid = threadIdx.x;
    int v = (tid < 640) ? g_part[tid] : 0;
    sm[tid] = v;
    __syncthreads();
    for (int ofs = 1; ofs < 1024; ofs <<= 1) {
        int t = (tid >= ofs) ? sm[tid - ofs] : 0;
        __syncthreads();
        sm[tid] += t;
        __syncthreads();
    }
    if (tid < 640) g_part[tid] = sm[tid] - v;   // exclusive
}

__global__ __launch_bounds__(1024) void scan3_kernel()
{
    int i = blockIdx.x * 1024 + threadIdx.x;
    int o = g_off[i] + g_part[blockIdx.x];
    g_off[i] = o;
    g_cur[i] = o;
}

__global__ __launch_bounds__(256) void scatter_kernel(
    const int* __restrict__ e_src, const int* __restrict__ e_dst)
{
    int e = blockIdx.x * 256 + threadIdx.x;
    int blk = e / EE;
    int row = c_blkoff[blk] + __ldg(e_dst + e);
    int pos = atomicAdd(&g_cur[row], 1);
    g_sorted_src[pos] = __ldg(e_src + e);
}

// ---------------- Phase B+C fused: warp per destination row, fp16 gather ----------------
__global__ __launch_bounds__(256) void agg_combine(
    float* __restrict__ out, const int* __restrict__ merge)
{
    const int lane = threadIdx.x & 31;
    const int r = blockIdx.x * 8 + (threadIdx.x >> 5);    // flat row 0..TOTAL_ROWS-1

    int blk = 0;
#pragma unroll
    for (int k = 1; k < 16; k++)
        if (r >= c_blkoff[k]) blk = k;
    const int s = blk >> 2, d = blk & 3;
    const int lrow = r - c_blkoff[blk];

    const int base = g_off[r];
    const int deg  = g_cnt[r];
    const uint2* FNs = (const uint2*)(g_FN + (size_t)s * NN * OO);   // 32 uint2 (4 halves each) per row

    float4 acc = make_float4(0.f, 0.f, 0.f, 0.f);
    for (int i0 = 0; i0 < deg; i0 += 32) {
        int mi = i0 + lane;
        int msrc = (mi < deg) ? __ldg(g_sorted_src + base + mi) : 0;
        int cnt = min(32, deg - i0);
        for (int j = 0; j < cnt; j++) {
            int src = __shfl_sync(0xffffffffu, msrc, j);
            uint2 raw = __ldg(FNs + (size_t)src * 32 + lane);
            __half2 h0 = *(__half2*)&raw.x;
            __half2 h1 = *(__half2*)&raw.y;
            float2 f0 = __half22float2(h0);
            float2 f1 = __half22float2(h1);
            acc.x += f0.x; acc.y += f0.y; acc.z += f1.x; acc.w += f1.y;
        }
    }

    const float invd = (deg > 0) ? (1.0f / (float)deg) : 0.0f;

    if (s == d) {
        if (deg == 0) return;  // nothing to add; Self already in out
        float* op = out + ((size_t)d * NN + lrow) * OO + lane * 4;
        asm volatile("red.global.add.v4.f32 [%0], {%1,%2,%3,%4};"
                     :: "l"(op), "f"(acc.x * invd), "f"(acc.y * invd),
                        "f"(acc.z * invd), "f"(acc.w * invd) : "memory");
    } else {
        float4 sm = ((const float4*)(g_SelfM + ((size_t)s * MM + lrow) * OO))[lane];
        float4 v;
        v.x = fmaf(acc.x, invd, sm.x);
        v.y = fmaf(acc.y, invd, sm.y);
        v.z = fmaf(acc.z, invd, sm.z);
        v.w = fmaf(acc.w, invd, sm.w);
        int tgt = __ldg(merge + (size_t)blk * MM + lrow);
        float* op = out + ((size_t)d * NN + tgt) * OO + lane * 4;
        asm volatile("red.global.add.v4.f32 [%0], {%1,%2,%3,%4};"
                     :: "l"(op), "f"(v.x), "f"(v.y), "f"(v.z), "f"(v.w) : "memory");
    }
}

// ---------------- launch ----------------
extern "C" void kernel_launch(void* const* d_in, const int* in_sizes, int n_in,
                              void* d_out, int out_size)
{
    const float* feats  = (const float*)d_in[0];   // [P,N,D]
    const float* Wself  = (const float*)d_in[1];   // [P,D,O]
    const float* Wneigh = (const float*)d_in[2];   // [P,D,O]
    const float* bias   = (const float*)d_in[3];   // [P,O]
    const int*   e_src  = (const int*)d_in[4];     // [P,P,E]
    const int*   e_dst  = (const int*)d_in[5];     // [P,P,E]
    const int*   merge  = (const int*)d_in[6];     // [P,P,M]
    float* out = (float*)d_out;                    // [P,N,O]

    void* cntPtr = nullptr; cudaGetSymbolAddress(&cntPtr, g_cnt);
    cudaMemsetAsync(cntPtr, 0, sizeof(int) * (size_t)TOTAL_ROWS, 0);

    hist_kernel<<<NEDGES / 256, 256>>>(e_dst);
    scan1_kernel<<<TOTAL_ROWS / 1024, 1024>>>();
    scan2_kernel<<<1, 1024>>>();
    scan3_kernel<<<TOTAL_ROWS / 1024, 1024>>>();

    gemm_self_fn<<<dim3(NN / 128, 2, PP), 256>>>(feats, Wself, Wneigh, bias, out);

    scatter_kernel<<<NEDGES / 256, 256>>>(e_src, e_dst);

    agg_combine<<<TOTAL_ROWS / 8, 256>>>(out, merge);
}

// round 5
// speedup vs baseline: 2.5795x; 1.4083x over previous
#include <cuda_runtime.h>
#include <cuda_fp16.h>

#define PP 4
#define NN 65536
#define DD 128
#define OO 128
#define EE 500000
#define MM 32768
#define TOTAL_ROWS 655360   // 4*N + 12*M
#define NEDGES (16 * EE)    // 8,000,000

#define BM 128
#define BN 128
#define BK 32
#define AS_STRIDE 36        // pad: bank = (4r + c) % 32 -> conflict-free a-frag loads
#define BS_STRIDE 136       // pad: bank = (8k + n) % 32 -> conflict-free b-frag loads

// ---------------- scratch (static device arrays; no allocation) ----------------
__device__ __half g_FN[(size_t)PP * NN * OO];        // feats @ W_neigh, fp16 (67 MB)
__device__ float g_SelfM[(size_t)PP * MM * OO];      // (feats@W_self + b) rows [0,M) (67 MB)
__device__ int   g_cnt[TOTAL_ROWS];
__device__ int   g_off[TOTAL_ROWS];
__device__ int   g_cur[TOTAL_ROWS];
__device__ int   g_part[1024];
__device__ int   g_sorted_src[NEDGES];               // edge src ids sorted by dst row (32 MB)

__constant__ int c_blkoff[17] = {
    0,      65536,  98304,  131072,
    163840, 196608, 262144, 294912,
    327680, 360448, 393216, 458752,
    491520, 524288, 557056, 589824, 655360};

__device__ __forceinline__ unsigned f2tf32(float v) {
    unsigned r;
    asm("cvt.rna.tf32.f32 %0, %1;" : "=r"(r) : "f"(v));
    return r;
}

// ---------------- Phase A: tf32 tensor-core GEMM ----------------
// y==0: out[s] = feats[s]@Ws + b (fp32) + SelfM copy; y==1: FN[s] = feats[s]@Wn (fp16)
__global__ __launch_bounds__(256, 2) void gemm_self_fn(
    const float* __restrict__ feats, const float* __restrict__ Ws,
    const float* __restrict__ Wn, const float* __restrict__ bias,
    float* __restrict__ out)
{
    __shared__ unsigned As[BM][AS_STRIDE];
    __shared__ unsigned Bs[BK][BS_STRIDE];

    const int s    = blockIdx.z;
    const int row0 = blockIdx.x * BM;
    const bool isSelf = (blockIdx.y == 0);
    const float* A = feats + (size_t)s * NN * DD;
    const float* B = (isSelf ? Ws : Wn) + (size_t)s * DD * OO;

    const int t    = threadIdx.x;
    const int lane = t & 31;
    const int wid  = t >> 5;
    const int wm   = wid >> 1;        // 0..3 : 32-row band
    const int wn   = wid & 1;         // 0..1 : 64-col band

    float C[2][8][4];
#pragma unroll
    for (int mf = 0; mf < 2; mf++)
#pragma unroll
        for (int j = 0; j < 8; j++)
#pragma unroll
            for (int q = 0; q < 4; q++) C[mf][j][q] = 0.0f;

    for (int kt = 0; kt < DD; kt += BK) {
        // A slab: 128 rows x 32 k  (1024 float4, 4 per thread)
#pragma unroll
        for (int q = 0; q < 4; q++) {
            int i  = t + 256 * q;
            int r  = i >> 3;
            int k0 = (i & 7) * 4;
            float4 v = *(const float4*)(A + (size_t)(row0 + r) * DD + kt + k0);
            uint4 u = make_uint4(f2tf32(v.x), f2tf32(v.y), f2tf32(v.z), f2tf32(v.w));
            *(uint4*)&As[r][k0] = u;
        }
        // B slab: 32 k x 128 cols
#pragma unroll
        for (int q = 0; q < 4; q++) {
            int i  = t + 256 * q;
            int k  = i >> 5;
            int n0 = (i & 31) * 4;
            float4 v = *(const float4*)(B + (size_t)(kt + k) * OO + n0);
            uint4 u = make_uint4(f2tf32(v.x), f2tf32(v.y), f2tf32(v.z), f2tf32(v.w));
            *(uint4*)&Bs[k][n0] = u;
        }
        __syncthreads();

#pragma unroll
        for (int kk = 0; kk < BK; kk += 8) {
            unsigned a[2][4];
#pragma unroll
            for (int mf = 0; mf < 2; mf++) {
                int r = wm * 32 + mf * 16 + (lane >> 2);
                int kc = kk + (lane & 3);
                a[mf][0] = As[r][kc];
                a[mf][1] = As[r + 8][kc];
                a[mf][2] = As[r][kc + 4];
                a[mf][3] = As[r + 8][kc + 4];
            }
#pragma unroll
            for (int j = 0; j < 8; j++) {
                int n = wn * 64 + j * 8 + (lane >> 2);
                unsigned b0 = Bs[kk + (lane & 3)][n];
                unsigned b1 = Bs[kk + (lane & 3) + 4][n];
#pragma unroll
                for (int mf = 0; mf < 2; mf++) {
                    asm("mma.sync.aligned.m16n8k8.row.col.f32.tf32.tf32.f32 "
                        "{%0,%1,%2,%3}, {%4,%5,%6,%7}, {%8,%9}, {%0,%1,%2,%3};"
                        : "+f"(C[mf][j][0]), "+f"(C[mf][j][1]),
                          "+f"(C[mf][j][2]), "+f"(C[mf][j][3])
                        : "r"(a[mf][0]), "r"(a[mf][1]), "r"(a[mf][2]), "r"(a[mf][3]),
                          "r"(b0), "r"(b1));
                }
            }
        }
        __syncthreads();
    }

    // ---------------- epilogue ----------------
    const int col0 = wn * 64;
    if (isSelf) {
#pragma unroll
        for (int mf = 0; mf < 2; mf++) {
            int r0 = row0 + wm * 32 + mf * 16 + (lane >> 2);
#pragma unroll
            for (int j = 0; j < 8; j++) {
                int c = col0 + j * 8 + (lane & 3) * 2;
                float b0v = __ldg(bias + s * OO + c);
                float b1v = __ldg(bias + s * OO + c + 1);
                float2 v0 = make_float2(C[mf][j][0] + b0v, C[mf][j][1] + b1v);
                float2 v1 = make_float2(C[mf][j][2] + b0v, C[mf][j][3] + b1v);
                *(float2*)(out + ((size_t)s * NN + r0) * OO + c)     = v0;
                *(float2*)(out + ((size_t)s * NN + r0 + 8) * OO + c) = v1;
                if (r0 < MM) {
                    *(float2*)(g_SelfM + ((size_t)s * MM + r0) * OO + c)     = v0;
                    *(float2*)(g_SelfM + ((size_t)s * MM + r0 + 8) * OO + c) = v1;
                }
            }
        }
    } else {
#pragma unroll
        for (int mf = 0; mf < 2; mf++) {
            int r0 = row0 + wm * 32 + mf * 16 + (lane >> 2);
#pragma unroll
            for (int j = 0; j < 8; j++) {
                int c = col0 + j * 8 + (lane & 3) * 2;
                __half2 h0 = __floats2half2_rn(C[mf][j][0], C[mf][j][1]);
                __half2 h1 = __floats2half2_rn(C[mf][j][2], C[mf][j][3]);
                *(__half2*)(g_FN + ((size_t)s * NN + r0) * OO + c)     = h0;
                *(__half2*)(g_FN + ((size_t)s * NN + r0 + 8) * OO + c) = h1;
            }
        }
    }
}

// ---------------- Sort pipeline ----------------
__global__ __launch_bounds__(256) void hist_kernel(const int* __restrict__ e_dst)
{
    int e = blockIdx.x * 256 + threadIdx.x;
    int blk = e / EE;
    int row = c_blkoff[blk] + __ldg(e_dst + e);
    atomicAdd(&g_cnt[row], 1);
}

__global__ __launch_bounds__(1024) void scan1_kernel()
{
    __shared__ int sm[1024];
    int tid = threadIdx.x;
    int i = blockIdx.x * 1024 + tid;
    int v = g_cnt[i];
    sm[tid] = v;
    __syncthreads();
    for (int ofs = 1; ofs < 1024; ofs <<= 1) {
        int t = (tid >= ofs) ? sm[tid - ofs] : 0;
        __syncthreads();
        sm[tid] += t;
        __syncthreads();
    }
    g_off[i] = sm[tid] - v;               // exclusive
    if (tid == 1023) g_part[blockIdx.x] = sm[1023];
}

__global__ __launch_bounds__(1024) void scan2_kernel()
{
    __shared__ int sm[1024];
    int tid = threadIdx.x;
    int v = (tid < 640) ? g_part[tid] : 0;
    sm[tid] = v;
    __syncthreads();
    for (int ofs = 1; ofs < 1024; ofs <<= 1) {
        int t = (tid >= ofs) ? sm[tid - ofs] : 0;
        __syncthreads();
        sm[tid] += t;
        __syncthreads();
    }
    if (tid < 640) g_part[tid] = sm[tid] - v;   // exclusive
}

__global__ __launch_bounds__(1024) void scan3_kernel()
{
    int i = blockIdx.x * 1024 + threadIdx.x;
    int o = g_off[i] + g_part[blockIdx.x];
    g_off[i] = o;
    g_cur[i] = o;
}

__global__ __launch_bounds__(256) void scatter_kernel(
    const int* __restrict__ e_src, const int* __restrict__ e_dst)
{
    int e = blockIdx.x * 256 + threadIdx.x;
    int blk = e / EE;
    int row = c_blkoff[blk] + __ldg(e_dst + e);
    int pos = atomicAdd(&g_cur[row], 1);
    g_sorted_src[pos] = __ldg(e_src + e);
}

// ---------------- Phase B+C fused: warp per destination row, fp16 gather ----------------
__global__ __launch_bounds__(256) void agg_combine(
    float* __restrict__ out, const int* __restrict__ merge)
{
    const int lane = threadIdx.x & 31;
    const int r = blockIdx.x * 8 + (threadIdx.x >> 5);

    int blk = 0;
#pragma unroll
    for (int k = 1; k < 16; k++)
        if (r >= c_blkoff[k]) blk = k;
    const int s = blk >> 2, d = blk & 3;
    const int lrow = r - c_blkoff[blk];

    const int base = g_off[r];
    const int deg  = g_cnt[r];
    const uint2* FNs = (const uint2*)(g_FN + (size_t)s * NN * OO);

    float4 acc = make_float4(0.f, 0.f, 0.f, 0.f);
    for (int i0 = 0; i0 < deg; i0 += 32) {
        int mi = i0 + lane;
        int msrc = (mi < deg) ? __ldg(g_sorted_src + base + mi) : 0;
        int cnt = min(32, deg - i0);
        for (int j = 0; j < cnt; j++) {
            int src = __shfl_sync(0xffffffffu, msrc, j);
            uint2 raw = __ldg(FNs + (size_t)src * 32 + lane);
            __half2 h0 = *(__half2*)&raw.x;
            __half2 h1 = *(__half2*)&raw.y;
            float2 f0 = __half22float2(h0);
            float2 f1 = __half22float2(h1);
            acc.x += f0.x; acc.y += f0.y; acc.z += f1.x; acc.w += f1.y;
        }
    }

    const float invd = (deg > 0) ? (1.0f / (float)deg) : 0.0f;

    if (s == d) {
        if (deg == 0) return;
        float* op = out + ((size_t)d * NN + lrow) * OO + lane * 4;
        asm volatile("red.global.add.v4.f32 [%0], {%1,%2,%3,%4};"
                     :: "l"(op), "f"(acc.x * invd), "f"(acc.y * invd),
                        "f"(acc.z * invd), "f"(acc.w * invd) : "memory");
    } else {
        float4 sm = ((const float4*)(g_SelfM + ((size_t)s * MM + lrow) * OO))[lane];
        float4 v;
        v.x = fmaf(acc.x, invd, sm.x);
        v.y = fmaf(acc.y, invd, sm.y);
        v.z = fmaf(acc.z, invd, sm.z);
        v.w = fmaf(acc.w, invd, sm.w);
        int tgt = __ldg(merge + (size_t)blk * MM + lrow);
        float* op = out + ((size_t)d * NN + tgt) * OO + lane * 4;
        asm volatile("red.global.add.v4.f32 [%0], {%1,%2,%3,%4};"
                     :: "l"(op), "f"(v.x), "f"(v.y), "f"(v.z), "f"(v.w) : "memory");
    }
}

// ---------------- launch ----------------
extern "C" void kernel_launch(void* const* d_in, const int* in_sizes, int n_in,
                              void* d_out, int out_size)
{
    const float* feats  = (const float*)d_in[0];   // [P,N,D]
    const float* Wself  = (const float*)d_in[1];   // [P,D,O]
    const float* Wneigh = (const float*)d_in[2];   // [P,D,O]
    const float* bias   = (const float*)d_in[3];   // [P,O]
    const int*   e_src  = (const int*)d_in[4];     // [P,P,E]
    const int*   e_dst  = (const int*)d_in[5];     // [P,P,E]
    const int*   merge  = (const int*)d_in[6];     // [P,P,M]
    float* out = (float*)d_out;                    // [P,N,O]

    void* cntPtr = nullptr; cudaGetSymbolAddress(&cntPtr, g_cnt);
    cudaMemsetAsync(cntPtr, 0, sizeof(int) * (size_t)TOTAL_ROWS, 0);

    hist_kernel<<<NEDGES / 256, 256>>>(e_dst);
    scan1_kernel<<<TOTAL_ROWS / 1024, 1024>>>();
    scan2_kernel<<<1, 1024>>>();
    scan3_kernel<<<TOTAL_ROWS / 1024, 1024>>>();

    gemm_self_fn<<<dim3(NN / BM, 2, PP), 256>>>(feats, Wself, Wneigh, bias, out);

    scatter_kernel<<<NEDGES / 256, 256>>>(e_src, e_dst);

    agg_combine<<<TOTAL_ROWS / 8, 256>>>(out, merge);
}